// round 1
// baseline (speedup 1.0000x reference)
#include <cuda_runtime.h>
#include <math.h>

#define BATCH   4
#define NTOK    8192
#define CH      256
#define HEADS   8
#define DK      32
#define KQVROWS 768
#define NSPLIT  8

// ---- scratch (static device globals; no allocation in kernel_launch) ----
__device__ float g_kqv[(size_t)BATCH * KQVROWS * NTOK];          // K(0..255) Q(256..511) V(512..767) per batch
__device__ float g_ctxp[BATCH * HEADS * NSPLIT * DK * DK];       // partial exp(K) V^T sums
__device__ float g_zp[BATCH * HEADS * NSPLIT * DK];              // partial sum exp(K)
__device__ float g_M[BATCH * CH * CH];                           // folded Wr @ ctx^T matrix
__device__ float g_S[BATCH * HEADS * NTOK];                      // reciprocal of per-(b,h,s) sum exp(Q)

// ============================================================
// K1: [K;Q;V] = [Wk;Wq;Wv](768x256) @ X[b](256x8192) + bias
// 128x128 block tile, BK=8, 256 threads, 8x8 microtile
// ============================================================
__global__ __launch_bounds__(256) void kqv_gemm(
    const float* __restrict__ x,
    const float* __restrict__ Wk, const float* __restrict__ bk,
    const float* __restrict__ Wq, const float* __restrict__ bq,
    const float* __restrict__ Wv, const float* __restrict__ bv)
{
    __shared__ float As[8][128];
    __shared__ float Bs[8][128];

    const int b  = blockIdx.z;
    const int o0 = blockIdx.y * 128;
    const int s0 = blockIdx.x * 128;
    const int tid = threadIdx.x;
    const int ty = tid >> 4, tx = tid & 15;

    // A (weights) load mapping: 128 rows x 8 cols per k-iter
    const int aRow = tid >> 1;
    const int aCol = (tid & 1) * 4;
    const int oA = o0 + aRow;
    const float* Arow;
    if (oA < 256)      Arow = Wk + (size_t)oA * 256;
    else if (oA < 512) Arow = Wq + (size_t)(oA - 256) * 256;
    else               Arow = Wv + (size_t)(oA - 512) * 256;

    // B (x) load mapping: 8 rows x 128 cols per k-iter
    const int bRow = tid >> 5;
    const int bCol = (tid & 31) * 4;
    const float* Bbase = x + (size_t)b * CH * NTOK + s0 + bCol;

    float acc[8][8];
    #pragma unroll
    for (int i = 0; i < 8; i++)
        #pragma unroll
        for (int j = 0; j < 8; j++) acc[i][j] = 0.f;

    for (int c0 = 0; c0 < CH; c0 += 8) {
        float4 av  = *(const float4*)(Arow + c0 + aCol);
        float4 bv4 = *(const float4*)(Bbase + (size_t)(c0 + bRow) * NTOK);
        __syncthreads();
        As[aCol + 0][aRow] = av.x;
        As[aCol + 1][aRow] = av.y;
        As[aCol + 2][aRow] = av.z;
        As[aCol + 3][aRow] = av.w;
        *(float4*)&Bs[bRow][bCol] = bv4;
        __syncthreads();
        #pragma unroll
        for (int kk = 0; kk < 8; kk++) {
            float a[8], bb[8];
            #pragma unroll
            for (int i = 0; i < 8; i++) a[i] = As[kk][ty * 8 + i];
            #pragma unroll
            for (int j = 0; j < 8; j++) bb[j] = Bs[kk][tx * 8 + j];
            #pragma unroll
            for (int i = 0; i < 8; i++)
                #pragma unroll
                for (int j = 0; j < 8; j++) acc[i][j] += a[i] * bb[j];
        }
    }

    #pragma unroll
    for (int i = 0; i < 8; i++) {
        const int o = o0 + ty * 8 + i;
        float bias;
        if (o < 256)      bias = bk[o];
        else if (o < 512) bias = bq[o - 256];
        else              bias = bv[o - 512];
        float* dst = g_kqv + ((size_t)b * KQVROWS + o) * NTOK + s0 + tx * 8;
        float4 v0 = make_float4(acc[i][0] + bias, acc[i][1] + bias, acc[i][2] + bias, acc[i][3] + bias);
        float4 v1 = make_float4(acc[i][4] + bias, acc[i][5] + bias, acc[i][6] + bias, acc[i][7] + bias);
        *(float4*)(dst)     = v0;
        *(float4*)(dst + 4) = v1;
    }
}

// ============================================================
// K2: ctx partials: for (b,h,split):
//   ctxp[k][v] = sum_{s in split} exp(K[k,s]) * V[v,s],  zp[k] = sum exp(K[k,s])
// ============================================================
__global__ __launch_bounds__(256) void ctx_partial()
{
    const int split = blockIdx.x, h = blockIdx.y, b = blockIdx.z;
    __shared__ float Ke[32][65];
    __shared__ float Vs[32][65];
    const float* Kg = g_kqv + ((size_t)b * KQVROWS + h * 32) * NTOK;
    const float* Vg = g_kqv + ((size_t)b * KQVROWS + 512 + h * 32) * NTOK;
    const int tid = threadIdx.x;
    const int k = tid >> 3, v0 = (tid & 7) * 4;
    const int sbase = split * (NTOK / NSPLIT);

    float acc0 = 0.f, acc1 = 0.f, acc2 = 0.f, acc3 = 0.f, z = 0.f;

    for (int sc = 0; sc < NTOK / NSPLIT; sc += 64) {
        __syncthreads();
        for (int i = tid; i < 32 * 64; i += 256) {
            int r = i >> 6, s = i & 63;
            size_t off = (size_t)r * NTOK + sbase + sc + s;
            Ke[r][s] = expf(Kg[off]);
            Vs[r][s] = Vg[off];
        }
        __syncthreads();
        #pragma unroll 8
        for (int s = 0; s < 64; s++) {
            float e = Ke[k][s];
            z += e;
            acc0 += e * Vs[v0 + 0][s];
            acc1 += e * Vs[v0 + 1][s];
            acc2 += e * Vs[v0 + 2][s];
            acc3 += e * Vs[v0 + 3][s];
        }
    }

    float* cp = g_ctxp + ((((size_t)(b * HEADS + h) * NSPLIT + split) * 32 + k) * 32 + v0);
    cp[0] = acc0; cp[1] = acc1; cp[2] = acc2; cp[3] = acc3;
    if (v0 == 0)
        g_zp[((b * HEADS + h) * NSPLIT + split) * 32 + k] = z;
}

// ============================================================
// K3a: reduce partials -> ctx (normalized), then fold Wr:
//   M[b][o][h*32+k] = sum_v Wr[o][h*32+v] * ctx[b][h][k][v]
// one block per (b,h)
// ============================================================
__global__ __launch_bounds__(256) void make_M(const float* __restrict__ Wr)
{
    const int h = blockIdx.x & 7, b = blockIdx.x >> 3;
    __shared__ float ctxs[32][33];
    __shared__ float zsh[32];
    const int tid = threadIdx.x;

    if (tid < 32) {
        float zz = 0.f;
        for (int sp = 0; sp < NSPLIT; sp++)
            zz += g_zp[((b * HEADS + h) * NSPLIT + sp) * 32 + tid];
        zsh[tid] = 1.0f / zz;
    }
    __syncthreads();

    for (int i = tid; i < 1024; i += 256) {
        int k = i >> 5, v = i & 31;
        float ssum = 0.f;
        for (int sp = 0; sp < NSPLIT; sp++)
            ssum += g_ctxp[(((size_t)(b * HEADS + h) * NSPLIT + sp) * 32 + k) * 32 + v];
        ctxs[k][v] = ssum * zsh[k];
    }
    __syncthreads();

    float wr[32];
    const float* wrow = Wr + (size_t)tid * 256 + h * 32;
    #pragma unroll
    for (int v = 0; v < 32; v++) wr[v] = wrow[v];

    for (int k = 0; k < 32; k++) {
        float a = 0.f;
        #pragma unroll
        for (int v = 0; v < 32; v++) a += wr[v] * ctxs[k][v];
        g_M[((size_t)b * CH + tid) * CH + h * 32 + k] = a;
    }
}

// ============================================================
// K3b: g_S[b][h][s] = 1 / sum_k exp(Q[b][h*32+k][s])
// ============================================================
__global__ __launch_bounds__(256) void qsum()
{
    const int chunk = blockIdx.x, h = blockIdx.y, b = blockIdx.z;
    const int s = chunk * 256 + threadIdx.x;
    const float* Qg = g_kqv + ((size_t)b * KQVROWS + 256 + h * 32) * NTOK + s;
    float acc = 0.f;
    #pragma unroll
    for (int k = 0; k < 32; k++) acc += expf(Qg[(size_t)k * NTOK]);
    g_S[((size_t)b * HEADS + h) * NTOK + s] = 1.0f / acc;
}

// ============================================================
// K4: out[b][s][o] = sum_g M[b][o][g] * exp(Q[g][s]) * g_S[b][g/32][s]
//                    + br[o] + x[b][o][s]
// ============================================================
__global__ __launch_bounds__(256) void out_gemm(
    const float* __restrict__ x, const float* __restrict__ br,
    float* __restrict__ out)
{
    __shared__ float As[8][128];
    __shared__ float Bs[8][128];

    const int b  = blockIdx.z;
    const int o0 = blockIdx.y * 128;
    const int s0 = blockIdx.x * 128;
    const int tid = threadIdx.x;
    const int ty = tid >> 4, tx = tid & 15;

    const int aRow = tid >> 1;
    const int aCol = (tid & 1) * 4;
    const float* Arow = g_M + ((size_t)b * CH + o0 + aRow) * CH;

    const int bRow = tid >> 5;
    const int bCol = (tid & 31) * 4;

    float acc[8][8];
    #pragma unroll
    for (int i = 0; i < 8; i++)
        #pragma unroll
        for (int j = 0; j < 8; j++) acc[i][j] = 0.f;

    for (int g0 = 0; g0 < CH; g0 += 8) {
        float4 av = *(const float4*)(Arow + g0 + aCol);
        const int g = g0 + bRow;
        const float* qptr = g_kqv + ((size_t)b * KQVROWS + 256 + g) * NTOK + s0 + bCol;
        const float* rptr = g_S + ((size_t)b * HEADS + (g >> 5)) * NTOK + s0 + bCol;
        float4 qv = *(const float4*)qptr;
        float4 rv = *(const float4*)rptr;
        float4 bn;
        bn.x = expf(qv.x) * rv.x;
        bn.y = expf(qv.y) * rv.y;
        bn.z = expf(qv.z) * rv.z;
        bn.w = expf(qv.w) * rv.w;
        __syncthreads();
        As[aCol + 0][aRow] = av.x;
        As[aCol + 1][aRow] = av.y;
        As[aCol + 2][aRow] = av.z;
        As[aCol + 3][aRow] = av.w;
        *(float4*)&Bs[bRow][bCol] = bn;
        __syncthreads();
        #pragma unroll
        for (int kk = 0; kk < 8; kk++) {
            float a[8], bb[8];
            #pragma unroll
            for (int i = 0; i < 8; i++) a[i] = As[kk][ty * 8 + i];
            #pragma unroll
            for (int j = 0; j < 8; j++) bb[j] = Bs[kk][tx * 8 + j];
            #pragma unroll
            for (int i = 0; i < 8; i++)
                #pragma unroll
                for (int j = 0; j < 8; j++) acc[i][j] += a[i] * bb[j];
        }
    }

    // epilogue: + br[o] + x[b][o][s], store transposed out[b][s][o]
    float res[8][8];
    #pragma unroll
    for (int i = 0; i < 8; i++) {
        const int o = o0 + ty * 8 + i;
        const float* xr = x + ((size_t)b * CH + o) * NTOK + s0 + tx * 8;
        float4 r0 = *(const float4*)(xr);
        float4 r1 = *(const float4*)(xr + 4);
        res[i][0] = r0.x; res[i][1] = r0.y; res[i][2] = r0.z; res[i][3] = r0.w;
        res[i][4] = r1.x; res[i][5] = r1.y; res[i][6] = r1.z; res[i][7] = r1.w;
    }
    float bias[8];
    #pragma unroll
    for (int i = 0; i < 8; i++) bias[i] = br[o0 + ty * 8 + i];

    #pragma unroll
    for (int j = 0; j < 8; j++) {
        const int s = s0 + tx * 8 + j;
        float* dst = out + ((size_t)b * NTOK + s) * CH + o0 + ty * 8;
        float4 v0 = make_float4(acc[0][j] + bias[0] + res[0][j],
                                acc[1][j] + bias[1] + res[1][j],
                                acc[2][j] + bias[2] + res[2][j],
                                acc[3][j] + bias[3] + res[3][j]);
        float4 v1 = make_float4(acc[4][j] + bias[4] + res[4][j],
                                acc[5][j] + bias[5] + res[5][j],
                                acc[6][j] + bias[6] + res[6][j],
                                acc[7][j] + bias[7] + res[7][j]);
        *(float4*)(dst)     = v0;
        *(float4*)(dst + 4) = v1;
    }
}

// ============================================================
extern "C" void kernel_launch(void* const* d_in, const int* in_sizes, int n_in,
                              void* d_out, int out_size)
{
    const float* x  = (const float*)d_in[0];
    const float* Wk = (const float*)d_in[1];
    const float* bk = (const float*)d_in[2];
    const float* Wq = (const float*)d_in[3];
    const float* bq = (const float*)d_in[4];
    const float* Wv = (const float*)d_in[5];
    const float* bv = (const float*)d_in[6];
    const float* Wr = (const float*)d_in[7];
    const float* br = (const float*)d_in[8];
    float* out = (float*)d_out;

    kqv_gemm<<<dim3(64, 6, 4), 256>>>(x, Wk, bk, Wq, bq, Wv, bv);
    ctx_partial<<<dim3(NSPLIT, HEADS, BATCH), 256>>>();
    qsum<<<dim3(32, HEADS, BATCH), 256>>>();
    make_M<<<32, 256>>>(Wr);
    out_gemm<<<dim3(64, 2, 4), 256>>>(x, br, out);
}

// round 2
// speedup vs baseline: 4.1931x; 4.1931x over previous
#include <cuda_runtime.h>
#include <cuda_bf16.h>
#include <math.h>
#include <stdint.h>

#define BATCH   4
#define NTOK    8192
#define CH      256
#define HEADS   8
#define KQVROWS 768
#define NSPL    32          // s-splits for ctx

// ---------------- scratch ----------------
__device__ __nv_bfloat16 g_kqvb[(size_t)BATCH * KQVROWS * NTOK]; // expK(0..255) expQ->Qn(256..511) V(512..767)
__device__ float g_ctxp[BATCH * HEADS * NSPL * 32 * 32];         // partial expK @ V^T
__device__ float g_zp[BATCH * HEADS * NSPL * 32];                // partial sum expK
__device__ float g_ctx[BATCH * HEADS * 32 * 32];                 // normalized ctx
__device__ __nv_bfloat16 g_Mbf[BATCH * CH * CH];                 // folded Wr @ ctx^T (bf16)

// ---------------- helpers ----------------
__device__ __forceinline__ uint32_t smem_u32(const void* p) {
    return (uint32_t)__cvta_generic_to_shared(p);
}
__device__ __forceinline__ void ldsm_x4(uint32_t& r0, uint32_t& r1, uint32_t& r2, uint32_t& r3, uint32_t a) {
    asm volatile("ldmatrix.sync.aligned.m8n8.x4.shared.b16 {%0,%1,%2,%3},[%4];"
                 : "=r"(r0), "=r"(r1), "=r"(r2), "=r"(r3) : "r"(a));
}
__device__ __forceinline__ void ldsm_x2(uint32_t& r0, uint32_t& r1, uint32_t a) {
    asm volatile("ldmatrix.sync.aligned.m8n8.x2.shared.b16 {%0,%1},[%2];"
                 : "=r"(r0), "=r"(r1) : "r"(a));
}
__device__ __forceinline__ void ldsm_x2t(uint32_t& r0, uint32_t& r1, uint32_t a) {
    asm volatile("ldmatrix.sync.aligned.m8n8.x2.trans.shared.b16 {%0,%1},[%2];"
                 : "=r"(r0), "=r"(r1) : "r"(a));
}
__device__ __forceinline__ void mma16816(float* c, uint32_t a0, uint32_t a1, uint32_t a2, uint32_t a3,
                                         uint32_t b0, uint32_t b1) {
    asm volatile("mma.sync.aligned.m16n8k16.row.col.f32.bf16.bf16.f32 "
                 "{%0,%1,%2,%3},{%4,%5,%6,%7},{%8,%9},{%0,%1,%2,%3};"
                 : "+f"(c[0]), "+f"(c[1]), "+f"(c[2]), "+f"(c[3])
                 : "r"(a0), "r"(a1), "r"(a2), "r"(a3), "r"(b0), "r"(b1));
}
__device__ __forceinline__ uint32_t f2bf2(float x, float y) {
    __nv_bfloat162 h = __float22bfloat162_rn(make_float2(x, y));
    return *reinterpret_cast<uint32_t*>(&h);
}

#define LDA 40    // 32 + 8 pad (bf16 elems)
#define LDB 136   // 128 + 8 pad

// ============================================================
// K1: [expK; expQ; V](768 x 8192) = transform( [Wk;Wq;Wv] @ X + b )
// grid (64, 6, 4), 256 thr. blocktile 128x128, BK=32, warps 2x4 (64x32 tiles)
// ============================================================
__global__ __launch_bounds__(256) void kqv_gemm(
    const float* __restrict__ x,
    const float* __restrict__ Wk, const float* __restrict__ bk,
    const float* __restrict__ Wq, const float* __restrict__ bq,
    const float* __restrict__ Wv, const float* __restrict__ bv)
{
    __shared__ __nv_bfloat16 As[128 * LDA];
    __shared__ __nv_bfloat16 Bs[32 * LDB];

    const int b    = blockIdx.z;
    const int type = blockIdx.y >> 1;             // 0=K 1=Q 2=V
    const int o_in = (blockIdx.y & 1) * 128;      // row offset within the 256-row W
    const float* W    = (type == 0) ? Wk : (type == 1) ? Wq : Wv;
    const float* bias = (type == 0) ? bk : (type == 1) ? bq : bv;
    const int s0  = blockIdx.x * 128;
    const int tid = threadIdx.x;

    // loaders
    const int aRow = tid >> 1, aCol = (tid & 1) * 16;
    const float* Ag = W + (size_t)(o_in + aRow) * 256 + aCol;
    const int bRow = tid >> 3, bCol = (tid & 7) * 4;
    const float* Bg = x + ((size_t)b * CH + bRow) * NTOK + s0 + bCol;

    float4 ra[4], rb[4];
    #pragma unroll
    for (int i = 0; i < 4; i++) ra[i] = *(const float4*)(Ag + 4 * i);
    #pragma unroll
    for (int i = 0; i < 4; i++) rb[i] = *(const float4*)(Bg + 32 * i);

    float acc[4][4][4];
    #pragma unroll
    for (int i = 0; i < 4; i++)
        #pragma unroll
        for (int j = 0; j < 4; j++)
            #pragma unroll
            for (int k = 0; k < 4; k++) acc[i][j][k] = 0.f;

    const int w = tid >> 5, L = tid & 31;
    const int wm = (w >> 2) * 64, wn = (w & 3) * 32;
    const int aRowF = L & 15, aColF = (L >> 4) * 8;
    const int bRowF = L & 15;

    for (int kb = 0; kb < 8; kb++) {
        if (kb) __syncthreads();
        #pragma unroll
        for (int i = 0; i < 4; i++) {
            uint2 u = make_uint2(f2bf2(ra[i].x, ra[i].y), f2bf2(ra[i].z, ra[i].w));
            *(uint2*)&As[aRow * LDA + aCol + 4 * i] = u;
        }
        #pragma unroll
        for (int i = 0; i < 4; i++) {
            uint2 u = make_uint2(f2bf2(rb[i].x, rb[i].y), f2bf2(rb[i].z, rb[i].w));
            *(uint2*)&Bs[bRow * LDB + bCol + 32 * i] = u;
        }
        __syncthreads();
        if (kb < 7) {
            Ag += 32; Bg += (size_t)32 * NTOK;
            #pragma unroll
            for (int i = 0; i < 4; i++) ra[i] = *(const float4*)(Ag + 4 * i);
            #pragma unroll
            for (int i = 0; i < 4; i++) rb[i] = *(const float4*)(Bg + 32 * i);
        }
        #pragma unroll
        for (int ks = 0; ks < 2; ks++) {
            uint32_t af[4][4], bf[4][2];
            #pragma unroll
            for (int mi = 0; mi < 4; mi++)
                ldsm_x4(af[mi][0], af[mi][1], af[mi][2], af[mi][3],
                        smem_u32(&As[(wm + mi * 16 + aRowF) * LDA + ks * 16 + aColF]));
            #pragma unroll
            for (int ni = 0; ni < 4; ni++)
                ldsm_x2t(bf[ni][0], bf[ni][1],
                         smem_u32(&Bs[(ks * 16 + bRowF) * LDB + wn + ni * 8]));
            #pragma unroll
            for (int mi = 0; mi < 4; mi++)
                #pragma unroll
                for (int ni = 0; ni < 4; ni++)
                    mma16816(acc[mi][ni], af[mi][0], af[mi][1], af[mi][2], af[mi][3],
                             bf[ni][0], bf[ni][1]);
        }
    }

    // epilogue: +bias, exp for K/Q, store bf16
    const int g = L >> 2, q = L & 3;
    const bool doExp = (type < 2);
    const int orow_base = type * 256 + o_in;
    #pragma unroll
    for (int mi = 0; mi < 4; mi++) {
        const int ol = wm + mi * 16 + g;
        const float b1 = bias[o_in + ol];
        const float b2 = bias[o_in + ol + 8];
        #pragma unroll
        for (int ni = 0; ni < 4; ni++) {
            float v0 = acc[mi][ni][0] + b1, v1 = acc[mi][ni][1] + b1;
            float v2 = acc[mi][ni][2] + b2, v3 = acc[mi][ni][3] + b2;
            if (doExp) { v0 = expf(v0); v1 = expf(v1); v2 = expf(v2); v3 = expf(v3); }
            const int scol = s0 + wn + ni * 8 + 2 * q;
            size_t i0 = ((size_t)b * KQVROWS + orow_base + ol) * NTOK + scol;
            size_t i1 = ((size_t)b * KQVROWS + orow_base + ol + 8) * NTOK + scol;
            *reinterpret_cast<uint32_t*>(&g_kqvb[i0]) = f2bf2(v0, v1);
            *reinterpret_cast<uint32_t*>(&g_kqvb[i1]) = f2bf2(v2, v3);
        }
    }
}

// ============================================================
// K2: ctx partials via MMA. grid (NSPL, BATCH), 256 thr.
// warp w = head h. A = expK[32 x s], B = V^T with ones column -> z free.
// ============================================================
__global__ __launch_bounds__(256) void ctx_mma()
{
    __shared__ __nv_bfloat16 Ke[256 * LDA];       // [row 0..255][32 s + pad]
    __shared__ __nv_bfloat16 Vs[8 * 40 * LDA];    // per head: [40 rows (32 V + ones/zeros)][32 s + pad]

    const int split = blockIdx.x, b = blockIdx.y;
    const int tid = threadIdx.x;
    const int h = tid >> 5, L = tid & 31;
    const int sbase = split * (NTOK / NSPL);      // 256 tokens per block

    // init ones rows (rows 32..39 of each head's V slab)
    for (int i = tid; i < 8 * 8 * LDA; i += 256) {
        int hh = i / (8 * LDA); int rem = i % (8 * LDA);
        int rr = rem / LDA; int c = rem % LDA;
        Vs[hh * 40 * LDA + (32 + rr) * LDA + c] =
            (rr == 0 && c < 32) ? __float2bfloat16(1.0f) : __float2bfloat16(0.0f);
    }

    const int lRow = tid >> 1, lHalf = (tid & 1) * 16;
    const __nv_bfloat16* Kg = g_kqvb + ((size_t)b * KQVROWS) * NTOK + sbase;         // rows 0..255
    const __nv_bfloat16* Vg = g_kqvb + ((size_t)b * KQVROWS + 512) * NTOK + sbase;   // rows 0..255

    uint4 pk[2][2], pv[2][2];
    #pragma unroll
    for (int j = 0; j < 2; j++) {
        const __nv_bfloat16* kp = Kg + (size_t)(lRow + 128 * j) * NTOK + lHalf;
        const __nv_bfloat16* vp = Vg + (size_t)(lRow + 128 * j) * NTOK + lHalf;
        pk[j][0] = *(const uint4*)(kp);     pk[j][1] = *(const uint4*)(kp + 8);
        pv[j][0] = *(const uint4*)(vp);     pv[j][1] = *(const uint4*)(vp + 8);
    }

    float acc[2][5][4];
    #pragma unroll
    for (int i = 0; i < 2; i++)
        #pragma unroll
        for (int j = 0; j < 5; j++)
            #pragma unroll
            for (int k = 0; k < 4; k++) acc[i][j][k] = 0.f;

    const int aRowF = L & 15, aColF = (L >> 4) * 8;
    const int bRowF = L & 7,  bColF = ((L >> 3) & 1) * 8;

    for (int ch = 0; ch < 8; ch++) {
        __syncthreads();
        #pragma unroll
        for (int j = 0; j < 2; j++) {
            int row = lRow + 128 * j;
            *(uint4*)&Ke[row * LDA + lHalf]     = pk[j][0];
            *(uint4*)&Ke[row * LDA + lHalf + 8] = pk[j][1];
            int vh = row >> 5, vv = row & 31;
            *(uint4*)&Vs[(vh * 40 + vv) * LDA + lHalf]     = pv[j][0];
            *(uint4*)&Vs[(vh * 40 + vv) * LDA + lHalf + 8] = pv[j][1];
        }
        __syncthreads();
        if (ch < 7) {
            #pragma unroll
            for (int j = 0; j < 2; j++) {
                const __nv_bfloat16* kp = Kg + (size_t)(lRow + 128 * j) * NTOK + (ch + 1) * 32 + lHalf;
                const __nv_bfloat16* vp = Vg + (size_t)(lRow + 128 * j) * NTOK + (ch + 1) * 32 + lHalf;
                pk[j][0] = *(const uint4*)(kp); pk[j][1] = *(const uint4*)(kp + 8);
                pv[j][0] = *(const uint4*)(vp); pv[j][1] = *(const uint4*)(vp + 8);
            }
        }
        #pragma unroll
        for (int ks = 0; ks < 2; ks++) {
            uint32_t af[2][4], bf[5][2];
            #pragma unroll
            for (int mi = 0; mi < 2; mi++)
                ldsm_x4(af[mi][0], af[mi][1], af[mi][2], af[mi][3],
                        smem_u32(&Ke[(h * 32 + mi * 16 + aRowF) * LDA + ks * 16 + aColF]));
            #pragma unroll
            for (int ni = 0; ni < 5; ni++)
                ldsm_x2(bf[ni][0], bf[ni][1],
                        smem_u32(&Vs[(h * 40 + ni * 8 + bRowF) * LDA + ks * 16 + bColF]));
            #pragma unroll
            for (int mi = 0; mi < 2; mi++)
                #pragma unroll
                for (int ni = 0; ni < 5; ni++)
                    mma16816(acc[mi][ni], af[mi][0], af[mi][1], af[mi][2], af[mi][3],
                             bf[ni][0], bf[ni][1]);
        }
    }

    // write partials
    const int g = L >> 2, q = L & 3;
    float* cp = g_ctxp + (((size_t)(b * HEADS + h) * NSPL) + split) * 1024;
    #pragma unroll
    for (int mi = 0; mi < 2; mi++) {
        const int k0 = mi * 16 + g;
        #pragma unroll
        for (int ni = 0; ni < 4; ni++) {
            const int v = ni * 8 + 2 * q;
            *(float2*)&cp[k0 * 32 + v]       = make_float2(acc[mi][ni][0], acc[mi][ni][1]);
            *(float2*)&cp[(k0 + 8) * 32 + v] = make_float2(acc[mi][ni][2], acc[mi][ni][3]);
        }
        if (q == 0) {  // ones column -> z
            float* zp = g_zp + (((size_t)(b * HEADS + h) * NSPL) + split) * 32;
            zp[k0]     = acc[mi][4][0];
            zp[k0 + 8] = acc[mi][4][2];
        }
    }
}

// ============================================================
// K3: reduce ctx partials + normalize. grid 32 (b*8+h), 256 thr.
// ============================================================
__global__ __launch_bounds__(256) void ctx_reduce()
{
    const int bh = blockIdx.x;
    const int tid = threadIdx.x;
    __shared__ float zinv[32];
    if (tid < 32) {
        float z = 0.f;
        for (int sp = 0; sp < NSPL; sp++)
            z += g_zp[((size_t)bh * NSPL + sp) * 32 + tid];
        zinv[tid] = 1.0f / z;
    }
    __syncthreads();
    const int k = tid >> 3, v4 = (tid & 7) * 4;
    float4 s = make_float4(0.f, 0.f, 0.f, 0.f);
    for (int sp = 0; sp < NSPL; sp++) {
        float4 p = *(const float4*)&g_ctxp[((size_t)bh * NSPL + sp) * 1024 + k * 32 + v4];
        s.x += p.x; s.y += p.y; s.z += p.z; s.w += p.w;
    }
    const float zi = zinv[k];
    s.x *= zi; s.y *= zi; s.z *= zi; s.w *= zi;
    *(float4*)&g_ctx[(size_t)bh * 1024 + k * 32 + v4] = s;
}

// ============================================================
// K4: M[b][o][h*32+k] = sum_v Wr[o][h*32+v] * ctx[b][h][k][v]  -> bf16
// grid 128 (bh*4 + oq), 256 thr.
// ============================================================
__global__ __launch_bounds__(256) void make_M(const float* __restrict__ Wr)
{
    const int bh = blockIdx.x >> 2, oq = blockIdx.x & 3;
    const int b = bh >> 3, h = bh & 7;
    __shared__ float ctxs[32][33];
    const int tid = threadIdx.x;
    for (int i = tid; i < 1024; i += 256)
        ctxs[i >> 5][i & 31] = g_ctx[(size_t)bh * 1024 + i];
    __syncthreads();

    const int o = oq * 64 + (tid >> 2), kq = tid & 3;
    float wr[32];
    const float* wrow = Wr + (size_t)o * 256 + h * 32;
    #pragma unroll
    for (int v = 0; v < 32; v += 4) {
        float4 t = *(const float4*)(wrow + v);
        wr[v] = t.x; wr[v + 1] = t.y; wr[v + 2] = t.z; wr[v + 3] = t.w;
    }
    uint32_t packed[4];
    #pragma unroll
    for (int kk2 = 0; kk2 < 4; kk2++) {
        float r[2];
        #pragma unroll
        for (int half = 0; half < 2; half++) {
            const int k = kq * 8 + kk2 * 2 + half;
            float a = 0.f;
            #pragma unroll
            for (int v = 0; v < 32; v++) a += wr[v] * ctxs[k][v];
            r[half] = a;
        }
        packed[kk2] = f2bf2(r[0], r[1]);
    }
    uint4 u = make_uint4(packed[0], packed[1], packed[2], packed[3]);
    *(uint4*)&g_Mbf[((size_t)b * CH + o) * CH + h * 32 + kq * 8] = u;
}

// ============================================================
// K5: Qn = expQ / sum_k expQ, in place (bf16). grid (32, 8, 4), 256 thr.
// ============================================================
__global__ __launch_bounds__(256) void qsum()
{
    const int b = blockIdx.z, h = blockIdx.y;
    const int s = blockIdx.x * 256 + threadIdx.x;
    __nv_bfloat16* Qg = g_kqvb + ((size_t)b * KQVROWS + 256 + h * 32) * NTOK + s;
    float acc = 0.f;
    #pragma unroll
    for (int k = 0; k < 32; k++) acc += __bfloat162float(Qg[(size_t)k * NTOK]);
    const float r = 1.0f / acc;
    #pragma unroll
    for (int k = 0; k < 32; k++) {
        float v = __bfloat162float(Qg[(size_t)k * NTOK]) * r;
        Qg[(size_t)k * NTOK] = __float2bfloat16(v);
    }
}

// ============================================================
// K6: out[b][s][o] = (M @ Qn)[o][s] + br[o] + x[b][o][s]
// grid (64, 2, 4), 256 thr. Same tiling as K1, bf16 operands.
// ============================================================
__global__ __launch_bounds__(256) void out_gemm(
    const float* __restrict__ x, const float* __restrict__ br,
    float* __restrict__ out)
{
    __shared__ __nv_bfloat16 As[128 * LDA];
    __shared__ __nv_bfloat16 Bs[32 * LDB];

    const int b  = blockIdx.z;
    const int o0 = blockIdx.y * 128;
    const int s0 = blockIdx.x * 128;
    const int tid = threadIdx.x;

    const int aRow = tid >> 1, aCol = (tid & 1) * 16;
    const __nv_bfloat16* Ag = g_Mbf + ((size_t)b * CH + o0 + aRow) * CH + aCol;
    const int bRow = tid >> 3, bCol = (tid & 7) * 16;
    const __nv_bfloat16* Bg = g_kqvb + ((size_t)b * KQVROWS + 256 + bRow) * NTOK + s0 + bCol;

    uint4 ra[2], rb[2];
    ra[0] = *(const uint4*)(Ag);     ra[1] = *(const uint4*)(Ag + 8);
    rb[0] = *(const uint4*)(Bg);     rb[1] = *(const uint4*)(Bg + 8);

    float acc[4][4][4];
    #pragma unroll
    for (int i = 0; i < 4; i++)
        #pragma unroll
        for (int j = 0; j < 4; j++)
            #pragma unroll
            for (int k = 0; k < 4; k++) acc[i][j][k] = 0.f;

    const int w = tid >> 5, L = tid & 31;
    const int wm = (w >> 2) * 64, wn = (w & 3) * 32;
    const int aRowF = L & 15, aColF = (L >> 4) * 8;
    const int bRowF = L & 15;

    for (int kb = 0; kb < 8; kb++) {
        if (kb) __syncthreads();
        *(uint4*)&As[aRow * LDA + aCol]     = ra[0];
        *(uint4*)&As[aRow * LDA + aCol + 8] = ra[1];
        *(uint4*)&Bs[bRow * LDB + bCol]     = rb[0];
        *(uint4*)&Bs[bRow * LDB + bCol + 8] = rb[1];
        __syncthreads();
        if (kb < 7) {
            Ag += 32; Bg += (size_t)32 * NTOK;
            ra[0] = *(const uint4*)(Ag); ra[1] = *(const uint4*)(Ag + 8);
            rb[0] = *(const uint4*)(Bg); rb[1] = *(const uint4*)(Bg + 8);
        }
        #pragma unroll
        for (int ks = 0; ks < 2; ks++) {
            uint32_t af[4][4], bf[4][2];
            #pragma unroll
            for (int mi = 0; mi < 4; mi++)
                ldsm_x4(af[mi][0], af[mi][1], af[mi][2], af[mi][3],
                        smem_u32(&As[(wm + mi * 16 + aRowF) * LDA + ks * 16 + aColF]));
            #pragma unroll
            for (int ni = 0; ni < 4; ni++)
                ldsm_x2t(bf[ni][0], bf[ni][1],
                         smem_u32(&Bs[(ks * 16 + bRowF) * LDB + wn + ni * 8]));
            #pragma unroll
            for (int mi = 0; mi < 4; mi++)
                #pragma unroll
                for (int ni = 0; ni < 4; ni++)
                    mma16816(acc[mi][ni], af[mi][0], af[mi][1], af[mi][2], af[mi][3],
                             bf[ni][0], bf[ni][1]);
        }
    }

    // epilogue: + br + residual x, store transposed
    const int g = L >> 2, q = L & 3;
    #pragma unroll
    for (int mi = 0; mi < 4; mi++) {
        const int o1 = o0 + wm + mi * 16 + g;
        const int o2 = o1 + 8;
        const float b1 = br[o1], b2 = br[o2];
        #pragma unroll
        for (int ni = 0; ni < 4; ni++) {
            const int s = s0 + wn + ni * 8 + 2 * q;
            float2 x1 = *(const float2*)&x[((size_t)b * CH + o1) * NTOK + s];
            float2 x2 = *(const float2*)&x[((size_t)b * CH + o2) * NTOK + s];
            float v0 = acc[mi][ni][0] + b1 + x1.x;
            float v1 = acc[mi][ni][1] + b1 + x1.y;
            float v2 = acc[mi][ni][2] + b2 + x2.x;
            float v3 = acc[mi][ni][3] + b2 + x2.y;
            out[((size_t)b * NTOK + s) * CH + o1]     = v0;
            out[((size_t)b * NTOK + s + 1) * CH + o1] = v1;
            out[((size_t)b * NTOK + s) * CH + o2]     = v2;
            out[((size_t)b * NTOK + s + 1) * CH + o2] = v3;
        }
    }
}

// ============================================================
extern "C" void kernel_launch(void* const* d_in, const int* in_sizes, int n_in,
                              void* d_out, int out_size)
{
    const float* x  = (const float*)d_in[0];
    const float* Wk = (const float*)d_in[1];
    const float* bk = (const float*)d_in[2];
    const float* Wq = (const float*)d_in[3];
    const float* bq = (const float*)d_in[4];
    const float* Wv = (const float*)d_in[5];
    const float* bv = (const float*)d_in[6];
    const float* Wr = (const float*)d_in[7];
    const float* br = (const float*)d_in[8];
    float* out = (float*)d_out;

    kqv_gemm<<<dim3(64, 6, 4), 256>>>(x, Wk, bk, Wq, bq, Wv, bv);
    ctx_mma<<<dim3(NSPL, BATCH), 256>>>();
    ctx_reduce<<<32, 256>>>();
    make_M<<<128, 256>>>(Wr);
    qsum<<<dim3(32, HEADS, BATCH), 256>>>();
    out_gemm<<<dim3(64, 2, 4), 256>>>(x, br, out);
}

// round 4
// speedup vs baseline: 4.5682x; 1.0895x over previous
#include <cuda_runtime.h>
#include <cuda_bf16.h>
#include <math.h>
#include <stdint.h>

#define BATCH   4
#define NTOK    8192
#define CH      256
#define HEADS   8
#define KQVROWS 768
#define NSPL    32

// ---------------- scratch ----------------
__device__ __nv_bfloat16 g_Wb[KQVROWS * CH];                     // [Wk;Wq;Wv] bf16
__device__ __nv_bfloat16 g_xb[(size_t)BATCH * CH * NTOK];        // x bf16, same [b][c][s] layout
__device__ __nv_bfloat16 g_kqvb[(size_t)BATCH * KQVROWS * NTOK]; // expK(0..255) expQ(256..511) V(512..767)
__device__ float g_S[(size_t)BATCH * HEADS * NTOK];              // 1 / sum_k expQ
__device__ float g_ctxp[BATCH * HEADS * NSPL * 32 * 32];
__device__ float g_zp[BATCH * HEADS * NSPL * 32];
__device__ float g_ctx[BATCH * HEADS * 32 * 32];
__device__ __nv_bfloat16 g_Mbf[BATCH * CH * CH];                 // folded Wr@ctx^T bf16

// ---------------- helpers ----------------
__device__ __forceinline__ uint32_t smem_u32(const void* p) {
    return (uint32_t)__cvta_generic_to_shared(p);
}
__device__ __forceinline__ void ldsm_x4(uint32_t& r0, uint32_t& r1, uint32_t& r2, uint32_t& r3, uint32_t a) {
    asm volatile("ldmatrix.sync.aligned.m8n8.x4.shared.b16 {%0,%1,%2,%3},[%4];"
                 : "=r"(r0), "=r"(r1), "=r"(r2), "=r"(r3) : "r"(a));
}
__device__ __forceinline__ void ldsm_x2(uint32_t& r0, uint32_t& r1, uint32_t a) {
    asm volatile("ldmatrix.sync.aligned.m8n8.x2.shared.b16 {%0,%1},[%2];"
                 : "=r"(r0), "=r"(r1) : "r"(a));
}
__device__ __forceinline__ void ldsm_x2t(uint32_t& r0, uint32_t& r1, uint32_t a) {
    asm volatile("ldmatrix.sync.aligned.m8n8.x2.trans.shared.b16 {%0,%1},[%2];"
                 : "=r"(r0), "=r"(r1) : "r"(a));
}
__device__ __forceinline__ void mma16816(float* c, uint32_t a0, uint32_t a1, uint32_t a2, uint32_t a3,
                                         uint32_t b0, uint32_t b1) {
    asm volatile("mma.sync.aligned.m16n8k16.row.col.f32.bf16.bf16.f32 "
                 "{%0,%1,%2,%3},{%4,%5,%6,%7},{%8,%9},{%0,%1,%2,%3};"
                 : "+f"(c[0]), "+f"(c[1]), "+f"(c[2]), "+f"(c[3])
                 : "r"(a0), "r"(a1), "r"(a2), "r"(a3), "r"(b0), "r"(b1));
}
__device__ __forceinline__ uint32_t f2bf2(float x, float y) {
    __nv_bfloat162 h = __float22bfloat162_rn(make_float2(x, y));
    return *reinterpret_cast<uint32_t*>(&h);
}
__device__ __forceinline__ void cpasync16(uint32_t s, const void* g) {
    asm volatile("cp.async.ca.shared.global [%0],[%1],16;" :: "r"(s), "l"(g));
}
#define CP_COMMIT() asm volatile("cp.async.commit_group;" ::: "memory")
#define CP_WAIT1()  asm volatile("cp.async.wait_group 1;" ::: "memory")

#define LDA 40    // A smem row stride (bf16)
#define LDB 136   // B smem row stride

// ============================================================
// conv_w: [Wk;Wq;Wv] fp32 -> g_Wb bf16. grid 192
// ============================================================
__global__ __launch_bounds__(256) void conv_w(
    const float* __restrict__ Wk, const float* __restrict__ Wq, const float* __restrict__ Wv)
{
    int e4 = blockIdx.x * 256 + threadIdx.x;
    int row = e4 >> 6;
    int col = (e4 & 63) * 4;
    const float* src = (row < 256) ? (Wk + (size_t)row * 256)
                     : (row < 512) ? (Wq + (size_t)(row - 256) * 256)
                                   : (Wv + (size_t)(row - 512) * 256);
    float4 v = *(const float4*)(src + col);
    *(uint2*)&g_Wb[(size_t)row * 256 + col] = make_uint2(f2bf2(v.x, v.y), f2bf2(v.z, v.w));
}

// ============================================================
// conv_x: x fp32 -> g_xb bf16 (same layout). grid 4096, 2 batches/launch
// ============================================================
__global__ __launch_bounds__(256) void conv_x(const float* __restrict__ x, int half)
{
    size_t i4 = (size_t)half * 1048576 + (size_t)blockIdx.x * 256 + threadIdx.x;
    float4 v = ((const float4*)x)[i4];
    ((uint2*)g_xb)[i4] = make_uint2(f2bf2(v.x, v.y), f2bf2(v.z, v.w));
}

// ============================================================
// K1: kqv_gemm, bf16 operands, cp.async 2-stage. grid (64, 6, 4), 256 thr.
// ============================================================
__global__ __launch_bounds__(256) void kqv_gemm(
    const float* __restrict__ bk, const float* __restrict__ bq, const float* __restrict__ bv)
{
    __shared__ __nv_bfloat16 As[2][128 * LDA];
    __shared__ __nv_bfloat16 Bs[2][32 * LDB];

    const int b    = blockIdx.z;
    const int type = blockIdx.y >> 1;
    const int o_in = (blockIdx.y & 1) * 128;
    const int s0   = blockIdx.x * 128;
    const int tid  = threadIdx.x;

    const __nv_bfloat16* Ag = g_Wb + (size_t)(type * 256 + o_in) * 256;
    const __nv_bfloat16* Bg = g_xb + (size_t)b * CH * NTOK;

    const int aRow0 = tid >> 2, aK0 = (tid & 3) * 8;
    const int bRow0 = tid >> 4, bC0 = (tid & 15) * 8;

    auto load_stage = [&](int kb, int st) {
        const __nv_bfloat16* a0 = Ag + (size_t)aRow0 * 256 + kb * 32 + aK0;
        cpasync16(smem_u32(&As[st][aRow0 * LDA + aK0]), a0);
        cpasync16(smem_u32(&As[st][(aRow0 + 64) * LDA + aK0]), a0 + (size_t)64 * 256);
        const __nv_bfloat16* b0 = Bg + (size_t)(kb * 32 + bRow0) * NTOK + s0 + bC0;
        cpasync16(smem_u32(&Bs[st][bRow0 * LDB + bC0]), b0);
        cpasync16(smem_u32(&Bs[st][(bRow0 + 16) * LDB + bC0]), b0 + (size_t)16 * NTOK);
    };

    float acc[4][4][4];
    #pragma unroll
    for (int i = 0; i < 4; i++)
        #pragma unroll
        for (int j = 0; j < 4; j++)
            #pragma unroll
            for (int k = 0; k < 4; k++) acc[i][j][k] = 0.f;

    const int w = tid >> 5, L = tid & 31;
    const int wm = (w >> 2) * 64, wn = (w & 3) * 32;
    const int aRowF = L & 15, aColF = (L >> 4) * 8;
    const int bRowF = L & 15;

    load_stage(0, 0);
    CP_COMMIT();

    for (int kb = 0; kb < 8; kb++) {
        if (kb < 7) load_stage(kb + 1, (kb + 1) & 1);
        CP_COMMIT();
        CP_WAIT1();
        __syncthreads();
        const int st = kb & 1;
        #pragma unroll
        for (int ks = 0; ks < 2; ks++) {
            uint32_t af[4][4], bf[4][2];
            #pragma unroll
            for (int mi = 0; mi < 4; mi++)
                ldsm_x4(af[mi][0], af[mi][1], af[mi][2], af[mi][3],
                        smem_u32(&As[st][(wm + mi * 16 + aRowF) * LDA + ks * 16 + aColF]));
            #pragma unroll
            for (int ni = 0; ni < 4; ni++)
                ldsm_x2t(bf[ni][0], bf[ni][1],
                         smem_u32(&Bs[st][(ks * 16 + bRowF) * LDB + wn + ni * 8]));
            #pragma unroll
            for (int mi = 0; mi < 4; mi++)
                #pragma unroll
                for (int ni = 0; ni < 4; ni++)
                    mma16816(acc[mi][ni], af[mi][0], af[mi][1], af[mi][2], af[mi][3],
                             bf[ni][0], bf[ni][1]);
        }
        __syncthreads();
    }

    // epilogue: +bias, exp for K/Q, store bf16 [row][s]
    const float* bias = (type == 0) ? bk : (type == 1) ? bq : bv;
    const int g = L >> 2, q = L & 3;
    const bool doExp = (type < 2);
    const int orow_base = type * 256 + o_in;
    #pragma unroll
    for (int mi = 0; mi < 4; mi++) {
        const int ol = wm + mi * 16 + g;
        const float b1 = bias[o_in + ol];
        const float b2 = bias[o_in + ol + 8];
        #pragma unroll
        for (int ni = 0; ni < 4; ni++) {
            float v0 = acc[mi][ni][0] + b1, v1 = acc[mi][ni][1] + b1;
            float v2 = acc[mi][ni][2] + b2, v3 = acc[mi][ni][3] + b2;
            if (doExp) { v0 = expf(v0); v1 = expf(v1); v2 = expf(v2); v3 = expf(v3); }
            const int scol = s0 + wn + ni * 8 + 2 * q;
            size_t i0 = ((size_t)b * KQVROWS + orow_base + ol) * NTOK + scol;
            size_t i1 = ((size_t)b * KQVROWS + orow_base + ol + 8) * NTOK + scol;
            *reinterpret_cast<uint32_t*>(&g_kqvb[i0]) = f2bf2(v0, v1);
            *reinterpret_cast<uint32_t*>(&g_kqvb[i1]) = f2bf2(v2, v3);
        }
    }
}

// ============================================================
// K2: ctx partials via MMA (warp = head). grid (NSPL, BATCH), 256 thr.
// ============================================================
#define CLDA 40
__global__ __launch_bounds__(256) void ctx_mma()
{
    __shared__ __nv_bfloat16 Ke[256 * CLDA];
    __shared__ __nv_bfloat16 Vs[8 * 40 * CLDA];

    const int split = blockIdx.x, b = blockIdx.y;
    const int tid = threadIdx.x;
    const int h = tid >> 5, L = tid & 31;
    const int sbase = split * (NTOK / NSPL);

    for (int i = tid; i < 8 * 8 * CLDA; i += 256) {
        int hh = i / (8 * CLDA); int rem = i % (8 * CLDA);
        int rr = rem / CLDA; int c = rem % CLDA;
        Vs[hh * 40 * CLDA + (32 + rr) * CLDA + c] =
            (rr == 0 && c < 32) ? __float2bfloat16(1.0f) : __float2bfloat16(0.0f);
    }

    const int lRow = tid >> 1, lHalf = (tid & 1) * 16;
    const __nv_bfloat16* Kg = g_kqvb + ((size_t)b * KQVROWS) * NTOK + sbase;
    const __nv_bfloat16* Vg = g_kqvb + ((size_t)b * KQVROWS + 512) * NTOK + sbase;

    uint4 pk[2][2], pv[2][2];
    #pragma unroll
    for (int j = 0; j < 2; j++) {
        const __nv_bfloat16* kp = Kg + (size_t)(lRow + 128 * j) * NTOK + lHalf;
        const __nv_bfloat16* vp = Vg + (size_t)(lRow + 128 * j) * NTOK + lHalf;
        pk[j][0] = *(const uint4*)(kp); pk[j][1] = *(const uint4*)(kp + 8);
        pv[j][0] = *(const uint4*)(vp); pv[j][1] = *(const uint4*)(vp + 8);
    }

    float acc[2][5][4];
    #pragma unroll
    for (int i = 0; i < 2; i++)
        #pragma unroll
        for (int j = 0; j < 5; j++)
            #pragma unroll
            for (int k = 0; k < 4; k++) acc[i][j][k] = 0.f;

    const int aRowF = L & 15, aColF = (L >> 4) * 8;
    const int bRowF = L & 7, bColF = ((L >> 3) & 1) * 8;

    for (int ch = 0; ch < 8; ch++) {
        __syncthreads();
        #pragma unroll
        for (int j = 0; j < 2; j++) {
            int row = lRow + 128 * j;
            *(uint4*)&Ke[row * CLDA + lHalf]     = pk[j][0];
            *(uint4*)&Ke[row * CLDA + lHalf + 8] = pk[j][1];
            int vh = row >> 5, vv = row & 31;
            *(uint4*)&Vs[(vh * 40 + vv) * CLDA + lHalf]     = pv[j][0];
            *(uint4*)&Vs[(vh * 40 + vv) * CLDA + lHalf + 8] = pv[j][1];
        }
        __syncthreads();
        if (ch < 7) {
            #pragma unroll
            for (int j = 0; j < 2; j++) {
                const __nv_bfloat16* kp = Kg + (size_t)(lRow + 128 * j) * NTOK + (ch + 1) * 32 + lHalf;
                const __nv_bfloat16* vp = Vg + (size_t)(lRow + 128 * j) * NTOK + (ch + 1) * 32 + lHalf;
                pk[j][0] = *(const uint4*)(kp); pk[j][1] = *(const uint4*)(kp + 8);
                pv[j][0] = *(const uint4*)(vp); pv[j][1] = *(const uint4*)(vp + 8);
            }
        }
        #pragma unroll
        for (int ks = 0; ks < 2; ks++) {
            uint32_t af[2][4], bf[5][2];
            #pragma unroll
            for (int mi = 0; mi < 2; mi++)
                ldsm_x4(af[mi][0], af[mi][1], af[mi][2], af[mi][3],
                        smem_u32(&Ke[(h * 32 + mi * 16 + aRowF) * CLDA + ks * 16 + aColF]));
            #pragma unroll
            for (int ni = 0; ni < 5; ni++)
                ldsm_x2(bf[ni][0], bf[ni][1],
                        smem_u32(&Vs[(h * 40 + ni * 8 + bRowF) * CLDA + ks * 16 + bColF]));
            #pragma unroll
            for (int mi = 0; mi < 2; mi++)
                #pragma unroll
                for (int ni = 0; ni < 5; ni++)
                    mma16816(acc[mi][ni], af[mi][0], af[mi][1], af[mi][2], af[mi][3],
                             bf[ni][0], bf[ni][1]);
        }
    }

    const int g = L >> 2, q = L & 3;
    float* cp = g_ctxp + (((size_t)(b * HEADS + h) * NSPL) + split) * 1024;
    #pragma unroll
    for (int mi = 0; mi < 2; mi++) {
        const int k0 = mi * 16 + g;
        #pragma unroll
        for (int ni = 0; ni < 4; ni++) {
            const int v = ni * 8 + 2 * q;
            *(float2*)&cp[k0 * 32 + v]       = make_float2(acc[mi][ni][0], acc[mi][ni][1]);
            *(float2*)&cp[(k0 + 8) * 32 + v] = make_float2(acc[mi][ni][2], acc[mi][ni][3]);
        }
        if (q == 0) {
            float* zp = g_zp + (((size_t)(b * HEADS + h) * NSPL) + split) * 32;
            zp[k0]     = acc[mi][4][0];
            zp[k0 + 8] = acc[mi][4][2];
        }
    }
}

// ============================================================
__global__ __launch_bounds__(256) void ctx_reduce()
{
    const int bh = blockIdx.x;
    const int tid = threadIdx.x;
    __shared__ float zinv[32];
    if (tid < 32) {
        float z = 0.f;
        for (int sp = 0; sp < NSPL; sp++)
            z += g_zp[((size_t)bh * NSPL + sp) * 32 + tid];
        zinv[tid] = 1.0f / z;
    }
    __syncthreads();
    const int k = tid >> 3, v4 = (tid & 7) * 4;
    float4 s = make_float4(0.f, 0.f, 0.f, 0.f);
    for (int sp = 0; sp < NSPL; sp++) {
        float4 p = *(const float4*)&g_ctxp[((size_t)bh * NSPL + sp) * 1024 + k * 32 + v4];
        s.x += p.x; s.y += p.y; s.z += p.z; s.w += p.w;
    }
    const float zi = zinv[k];
    s.x *= zi; s.y *= zi; s.z *= zi; s.w *= zi;
    *(float4*)&g_ctx[(size_t)bh * 1024 + k * 32 + v4] = s;
}

// ============================================================
__global__ __launch_bounds__(256) void make_M(const float* __restrict__ Wr)
{
    const int bh = blockIdx.x >> 2, oq = blockIdx.x & 3;
    const int b = bh >> 3, h = bh & 7;
    __shared__ float ctxs[32][33];
    const int tid = threadIdx.x;
    for (int i = tid; i < 1024; i += 256)
        ctxs[i >> 5][i & 31] = g_ctx[(size_t)bh * 1024 + i];
    __syncthreads();

    const int o = oq * 64 + (tid >> 2), kq = tid & 3;
    float wr[32];
    const float* wrow = Wr + (size_t)o * 256 + h * 32;
    #pragma unroll
    for (int v = 0; v < 32; v += 4) {
        float4 t = *(const float4*)(wrow + v);
        wr[v] = t.x; wr[v + 1] = t.y; wr[v + 2] = t.z; wr[v + 3] = t.w;
    }
    uint32_t packed[4];
    #pragma unroll
    for (int kk2 = 0; kk2 < 4; kk2++) {
        float r[2];
        #pragma unroll
        for (int half = 0; half < 2; half++) {
            const int k = kq * 8 + kk2 * 2 + half;
            float a = 0.f;
            #pragma unroll
            for (int v = 0; v < 32; v++) a += wr[v] * ctxs[k][v];
            r[half] = a;
        }
        packed[kk2] = f2bf2(r[0], r[1]);
    }
    *(uint4*)&g_Mbf[((size_t)b * CH + o) * CH + h * 32 + kq * 8] =
        make_uint4(packed[0], packed[1], packed[2], packed[3]);
}

// ============================================================
// qsum: g_S = 1 / sum_k expQ. grid (32, 8, 4), 256 thr.
// ============================================================
__global__ __launch_bounds__(256) void qsum()
{
    const int b = blockIdx.z, h = blockIdx.y;
    const int s = blockIdx.x * 256 + threadIdx.x;
    const __nv_bfloat16* Qg = g_kqvb + ((size_t)b * KQVROWS + 256 + h * 32) * NTOK + s;
    float acc = 0.f;
    #pragma unroll
    for (int k = 0; k < 32; k++) acc += __bfloat162float(Qg[(size_t)k * NTOK]);
    g_S[((size_t)b * HEADS + h) * NTOK + s] = 1.0f / acc;
}

// ============================================================
// K6: out_gemm = M @ (expQ * g_S) + br + x, transposed store. grid (64, 2, 4)
// ============================================================
__global__ __launch_bounds__(256) void out_gemm(
    const float* __restrict__ x, const float* __restrict__ br,
    float* __restrict__ out)
{
    __shared__ __nv_bfloat16 As[128 * LDA];
    __shared__ __nv_bfloat16 Bs[32 * LDB];

    const int b  = blockIdx.z;
    const int o0 = blockIdx.y * 128;
    const int s0 = blockIdx.x * 128;
    const int tid = threadIdx.x;

    const int aRow = tid >> 1, aCol = (tid & 1) * 16;
    const __nv_bfloat16* Ag = g_Mbf + ((size_t)b * CH + o0 + aRow) * CH + aCol;
    const int bRow = tid >> 3, bCol = (tid & 7) * 16;
    const __nv_bfloat16* Bg = g_kqvb + ((size_t)b * KQVROWS + 256 + bRow) * NTOK + s0 + bCol;
    const float* Sg = g_S + ((size_t)b * HEADS) * NTOK + s0 + bCol;   // + kb*NTOK each kb (h == kb)

    uint4 ra[2], rb[2];
    float4 rs[4];
    ra[0] = *(const uint4*)(Ag); ra[1] = *(const uint4*)(Ag + 8);
    rb[0] = *(const uint4*)(Bg); rb[1] = *(const uint4*)(Bg + 8);
    #pragma unroll
    for (int i = 0; i < 4; i++) rs[i] = *(const float4*)(Sg + 4 * i);

    float acc[4][4][4];
    #pragma unroll
    for (int i = 0; i < 4; i++)
        #pragma unroll
        for (int j = 0; j < 4; j++)
            #pragma unroll
            for (int k = 0; k < 4; k++) acc[i][j][k] = 0.f;

    const int w = tid >> 5, L = tid & 31;
    const int wm = (w >> 2) * 64, wn = (w & 3) * 32;
    const int aRowF = L & 15, aColF = (L >> 4) * 8;
    const int bRowF = L & 15;

    for (int kb = 0; kb < 8; kb++) {
        if (kb) __syncthreads();
        *(uint4*)&As[aRow * LDA + aCol]     = ra[0];
        *(uint4*)&As[aRow * LDA + aCol + 8] = ra[1];
        // normalize expQ by g_S on the fly
        {
            const uint32_t* qp = (const uint32_t*)rb;
            const float* sp = (const float*)rs;
            uint32_t outp[8];
            #pragma unroll
            for (int j = 0; j < 8; j++) {
                __nv_bfloat162 h2 = *reinterpret_cast<const __nv_bfloat162*>(&qp[j]);
                outp[j] = f2bf2(__bfloat162float(h2.x) * sp[2 * j],
                                __bfloat162float(h2.y) * sp[2 * j + 1]);
            }
            *(uint4*)&Bs[bRow * LDB + bCol]     = make_uint4(outp[0], outp[1], outp[2], outp[3]);
            *(uint4*)&Bs[bRow * LDB + bCol + 8] = make_uint4(outp[4], outp[5], outp[6], outp[7]);
        }
        __syncthreads();
        if (kb < 7) {
            Ag += 32; Bg += (size_t)32 * NTOK; Sg += (size_t)NTOK;
            ra[0] = *(const uint4*)(Ag); ra[1] = *(const uint4*)(Ag + 8);
            rb[0] = *(const uint4*)(Bg); rb[1] = *(const uint4*)(Bg + 8);
            #pragma unroll
            for (int i = 0; i < 4; i++) rs[i] = *(const float4*)(Sg + 4 * i);
        }
        #pragma unroll
        for (int ks = 0; ks < 2; ks++) {
            uint32_t af[4][4], bf[4][2];
            #pragma unroll
            for (int mi = 0; mi < 4; mi++)
                ldsm_x4(af[mi][0], af[mi][1], af[mi][2], af[mi][3],
                        smem_u32(&As[(wm + mi * 16 + aRowF) * LDA + ks * 16 + aColF]));
            #pragma unroll
            for (int ni = 0; ni < 4; ni++)
                ldsm_x2t(bf[ni][0], bf[ni][1],
                         smem_u32(&Bs[(ks * 16 + bRowF) * LDB + wn + ni * 8]));
            #pragma unroll
            for (int mi = 0; mi < 4; mi++)
                #pragma unroll
                for (int ni = 0; ni < 4; ni++)
                    mma16816(acc[mi][ni], af[mi][0], af[mi][1], af[mi][2], af[mi][3],
                             bf[ni][0], bf[ni][1]);
        }
    }

    // epilogue: + br + residual x, store transposed
    const int g = L >> 2, q = L & 3;
    #pragma unroll
    for (int mi = 0; mi < 4; mi++) {
        const int o1 = o0 + wm + mi * 16 + g;
        const int o2 = o1 + 8;
        const float b1 = br[o1], b2 = br[o2];
        #pragma unroll
        for (int ni = 0; ni < 4; ni++) {
            const int s = s0 + wn + ni * 8 + 2 * q;
            float2 x1 = *(const float2*)&x[((size_t)b * CH + o1) * NTOK + s];
            float2 x2 = *(const float2*)&x[((size_t)b * CH + o2) * NTOK + s];
            float v0 = acc[mi][ni][0] + b1 + x1.x;
            float v1 = acc[mi][ni][1] + b1 + x1.y;
            float v2 = acc[mi][ni][2] + b2 + x2.x;
            float v3 = acc[mi][ni][3] + b2 + x2.y;
            out[((size_t)b * NTOK + s) * CH + o1]     = v0;
            out[((size_t)b * NTOK + s + 1) * CH + o1] = v1;
            out[((size_t)b * NTOK + s) * CH + o2]     = v2;
            out[((size_t)b * NTOK + s + 1) * CH + o2] = v3;
        }
    }
}

// ============================================================
extern "C" void kernel_launch(void* const* d_in, const int* in_sizes, int n_in,
                              void* d_out, int out_size)
{
    const float* x  = (const float*)d_in[0];
    const float* Wk = (const float*)d_in[1];
    const float* bk = (const float*)d_in[2];
    const float* Wq = (const float*)d_in[3];
    const float* bq = (const float*)d_in[4];
    const float* Wv = (const float*)d_in[5];
    const float* bv = (const float*)d_in[6];
    const float* Wr = (const float*)d_in[7];
    const float* br = (const float*)d_in[8];
    float* out = (float*)d_out;

    conv_w<<<192, 256>>>(Wk, Wq, Wv);                 // #1
    conv_x<<<4096, 256>>>(x, 0);                      // #2
    conv_x<<<4096, 256>>>(x, 1);                      // #3
    kqv_gemm<<<dim3(64, 6, 4), 256>>>(bk, bq, bv);    // #4  <- ncu target
    ctx_mma<<<dim3(NSPL, BATCH), 256>>>();
    ctx_reduce<<<32, 256>>>();
    make_M<<<128, 256>>>(Wr);
    qsum<<<dim3(32, HEADS, BATCH), 256>>>();
    out_gemm<<<dim3(64, 2, 4), 256>>>(x, br, out);
}